// round 11
// baseline (speedup 1.0000x reference)
#include <cuda_runtime.h>
#include <cuda_bf16.h>
#include <cstdint>

#define BB 32
#define NN 2048
#define DD 512
#define EE 512
#define VV 32000
#define TT 32
#define NSTEP 31
#define MM (NSTEP * BB)   // 992

typedef unsigned long long ull;

// ---------------- scratch ----------------------------------------------------
__device__ float g_Hall[MM * DD];
__device__ float g_HW[MM * DD];
__device__ float g_scores[MM * NN];         // 8.1 MB
__device__ float g_gx[MM * 4 * DD];         // 8.1 MB (x-gates+biases; RED-accumulated)
__device__ float g_h0part[4 * BB * DD];
__device__ float g_hc[16][1024];            // published h chunks [dt][b*32+dl]
__device__ float g_cntpad[BB];
__device__ float g_cntptr[BB];
__device__ int   g_mask_mode;
__device__ unsigned g_cnt[16 * 32];         // partial counters, 1 per 128B line
__device__ unsigned g_flag[16 * 32];        // h-chunk flags,    1 per 128B line
__device__ unsigned g_arrive;

// ---------------- helpers -----------------------------------------------------
__device__ __forceinline__ bool getmask(const void* p, int idx) {
    int m = g_mask_mode;
    if (m == 1) return ((const int*)p)[idx] != 0;
    if (m == 2) return ((const float*)p)[idx] != 0.0f;
    return ((const unsigned char*)p)[idx] != 0;
}
__device__ __forceinline__ float sigm(float x) { return 1.0f / (1.0f + expf(-x)); }

__device__ __forceinline__ ull ld2(const float* p) { return *(const ull*)p; }
__device__ __forceinline__ ull fma2(ull a, ull b, ull c) {
    ull d;
    asm("fma.rn.f32x2 %0, %1, %2, %3;" : "=l"(d) : "l"(a), "l"(b), "l"(c));
    return d;
}
__device__ __forceinline__ ull add2(ull a, ull b) {
    ull d;
    asm("add.rn.f32x2 %0, %1, %2;" : "=l"(d) : "l"(a), "l"(b));
    return d;
}
__device__ __forceinline__ float sum2(ull v) {
    return __uint_as_float((unsigned)v) + __uint_as_float((unsigned)(v >> 32));
}
__device__ __forceinline__ void poll_ge(unsigned* addr, unsigned target) {
    unsigned v;
    do {
        asm volatile("ld.acquire.gpu.global.u32 %0, [%1];"
                     : "=r"(v) : "l"(addr) : "memory");
    } while (v < target);
}
__device__ __forceinline__ void st_release(unsigned* addr, unsigned val) {
    asm volatile("st.release.gpu.global.u32 [%0], %1;" :: "l"(addr), "r"(val) : "memory");
}
__device__ __forceinline__ void red_add_f32(float* addr, float val) {
    asm volatile("red.global.add.f32 [%0], %1;" :: "l"(addr), "f"(val) : "memory");
}

// ---------------- setup kernels ----------------------------------------------
__global__ void detect_kernel(const int* pad_as_int) {
    int tid = threadIdx.x;
    if (tid < 16) { g_cnt[tid * 32] = 0; g_flag[tid * 32] = 0; }
    if (tid == 0) {
        int v = pad_as_int[0];
        g_mask_mode = (v == 1) ? 1 : ((v == 0x3F800000) ? 2 : 0);
        g_arrive = 0;
    }
}

__global__ void zero_kernel(float4* out, int n4) {
    int idx = blockIdx.x * blockDim.x + threadIdx.x;
    int stride = gridDim.x * blockDim.x;
    float4 z = {0.f, 0.f, 0.f, 0.f};
    for (int i = idx; i < n4; i += stride) out[i] = z;
}

__global__ void sos_kernel(float* out, const int* sosp) {
    int b = threadIdx.x;
    if (b < BB) out[(size_t)b * VV + sosp[0]] = 1.0f;
}

// ---------------- xgemm: gates_x[m][R] = emb[tok(m)]·W_ih[R] + b_ih + b_hh ---
__global__ void __launch_bounds__(256) xgemm_kernel(
        const float* __restrict__ emb, const float* __restrict__ Wih,
        const float* __restrict__ bih, const float* __restrict__ bhh,
        const int* __restrict__ target, const int* __restrict__ sosp) {
    __shared__ float Ws[2][64][34];
    __shared__ float Xs[2][64][34];
    __shared__ int toks[64];
    int tid = threadIdx.x;
    int Rbase = blockIdx.x * 64;
    int mbase = blockIdx.y * 64;
    if (tid < 64) {
        int m = mbase + tid;
        int t = m >> 5, b = m & 31;
        int tok = sosp[0];
        if (m < MM && t > 0) tok = target[t * BB + b];
        toks[tid] = tok;
    }
    __syncthreads();
    #pragma unroll
    for (int q = 0; q < 2; q++) {
        int i = tid + 256 * q;
        int row = i >> 3, c4 = i & 7;
        float4 w = *(const float4*)&Wih[(size_t)(Rbase + row) * 512 + c4 * 4];
        float4 x = *(const float4*)&emb[(size_t)toks[row] * 512 + c4 * 4];
        *(float2*)&Ws[0][row][c4 * 4]     = make_float2(w.x, w.y);
        *(float2*)&Ws[0][row][c4 * 4 + 2] = make_float2(w.z, w.w);
        *(float2*)&Xs[0][row][c4 * 4]     = make_float2(x.x, x.y);
        *(float2*)&Xs[0][row][c4 * 4 + 2] = make_float2(x.z, x.w);
    }
    __syncthreads();
    int rl = tid & 15, mg = tid >> 4;
    ull acc[4][4] = {};
    float4 wst[2], xst[2];
    for (int kt = 0; kt < 16; kt++) {
        int cur = kt & 1;
        if (kt < 15) {
            int k0 = (kt + 1) * 32;
            #pragma unroll
            for (int q = 0; q < 2; q++) {
                int i = tid + 256 * q;
                int row = i >> 3, c4 = i & 7;
                wst[q] = *(const float4*)&Wih[(size_t)(Rbase + row) * 512 + k0 + c4 * 4];
                xst[q] = *(const float4*)&emb[(size_t)toks[row] * 512 + k0 + c4 * 4];
            }
        }
        #pragma unroll
        for (int kp = 0; kp < 16; kp++) {
            ull wv[4], xv[4];
            #pragma unroll
            for (int i = 0; i < 4; i++) wv[i] = ld2(&Ws[cur][rl + 16 * i][kp * 2]);
            #pragma unroll
            for (int j = 0; j < 4; j++) xv[j] = ld2(&Xs[cur][mg * 4 + j][kp * 2]);
            #pragma unroll
            for (int i = 0; i < 4; i++)
                #pragma unroll
                for (int j = 0; j < 4; j++)
                    acc[i][j] = fma2(wv[i], xv[j], acc[i][j]);
        }
        if (kt < 15) {
            __syncthreads();
            int nb = cur ^ 1;
            #pragma unroll
            for (int q = 0; q < 2; q++) {
                int i = tid + 256 * q;
                int row = i >> 3, c4 = i & 7;
                *(float2*)&Ws[nb][row][c4 * 4]     = make_float2(wst[q].x, wst[q].y);
                *(float2*)&Ws[nb][row][c4 * 4 + 2] = make_float2(wst[q].z, wst[q].w);
                *(float2*)&Xs[nb][row][c4 * 4]     = make_float2(xst[q].x, xst[q].y);
                *(float2*)&Xs[nb][row][c4 * 4 + 2] = make_float2(xst[q].z, xst[q].w);
            }
            __syncthreads();
        }
    }
    #pragma unroll
    for (int j = 0; j < 4; j++) {
        int m = mbase + mg * 4 + j;
        if (m >= MM) continue;
        #pragma unroll
        for (int i = 0; i < 4; i++) {
            int R = Rbase + rl + 16 * i;
            g_gx[((size_t)m << 11) + R] = sum2(acc[i][j]) + bih[R] + bhh[R];
        }
    }
}

// ---- one-shot grid barrier for phase 0 (fence-all + single counter) ---------
__device__ __forceinline__ void gbar(unsigned target) {
    __threadfence();
    __syncthreads();
    if (threadIdx.x == 0) {
        asm volatile("red.release.gpu.global.add.u32 [%0], 1;"
                     :: "l"(&g_arrive) : "memory");
        poll_ge(&g_arrive, target);
    }
    __syncthreads();
}

// ---------------- persistent kernel: h0 + counts + dataflow LSTM -------------
// 128 blocks x 256 threads. block = (s = bid&7 k-slice, dt = bid>>3 d-tile).
// Owner(dt) = block (s = dt>>1, dt): accumulates gates, runs pointwise for its
// 32 d-columns, publishes 4KB h-chunk + flag. Non-owners RED partials into
// g_gx[t] and arrive on cnt[dt] (7 arrivals). NO grid-wide barrier in the loop.
__global__ void __launch_bounds__(256) lstm_persistent(
        const float* __restrict__ Whh, const float* __restrict__ enc,
        const void* pad, const void* ptrm) {
    __shared__ float Wsm[128][66];    // 33 KB
    __shared__ float hs[32][66];      // 8.25 KB
    __shared__ float psum[32][4][33]; // 16.5 KB (owner gate sums)
    __shared__ float hex[32][32];     // 4 KB (owner h chunk)
    __shared__ int red1[256], red2[256];
    int tid = threadIdx.x;
    int bid = blockIdx.x;
    int s  = bid & 7;
    int dt = bid >> 3;
    int k0 = s * 64;
    bool owner = (s == (dt >> 1));

    // ---- phase 0: h0 partial sums over enc + pointer counts ----
    {
        int b = bid >> 2, ns = bid & 3;
        int d0 = tid * 2;
        int base = b * NN + ns * 512;
        ull a0 = 0, a1 = 0, a2 = 0, a3 = 0;
        for (int n = 0; n < 512; n += 4) {
            int i0 = base + n;
            if (getmask(pad, i0))     a0 = add2(a0, ld2(&enc[(size_t)(i0) * DD + d0]));
            if (getmask(pad, i0 + 1)) a1 = add2(a1, ld2(&enc[(size_t)(i0 + 1) * DD + d0]));
            if (getmask(pad, i0 + 2)) a2 = add2(a2, ld2(&enc[(size_t)(i0 + 2) * DD + d0]));
            if (getmask(pad, i0 + 3)) a3 = add2(a3, ld2(&enc[(size_t)(i0 + 3) * DD + d0]));
        }
        *(ull*)&g_h0part[(ns * BB + b) * DD + d0] = add2(add2(a0, a1), add2(a2, a3));
        if (ns == 0) {
            int c1 = 0, c2 = 0;
            for (int n = tid; n < NN; n += 256) {
                c1 += getmask(pad, b * NN + n) ? 1 : 0;
                c2 += getmask(ptrm, b * NN + n) ? 1 : 0;
            }
            red1[tid] = c1; red2[tid] = c2; __syncthreads();
            for (int st = 128; st > 0; st >>= 1) {
                if (tid < st) { red1[tid] += red1[tid + st]; red2[tid] += red2[tid + st]; }
                __syncthreads();
            }
            if (tid == 0) { g_cntpad[b] = (float)red1[0]; g_cntptr[b] = (float)red2[0]; }
        }
    }
    gbar(128);

    // ---- W_hh slice into smem once: lr = g*32+dl -> R = g*512 + 32dt + dl ---
    for (int i = tid; i < 128 * 64; i += 256) {
        int lr = i >> 6, kk = i & 63;
        int R = ((lr >> 5) << 9) + (dt << 5) + (lr & 31);
        Wsm[lr][kk] = Whh[(size_t)R * 512 + k0 + kk];
    }

    int pb = tid & 31, dl0 = tid >> 5;
    float creg[4] = {0.f, 0.f, 0.f, 0.f};

    // ---- owner: h0 chunk + publish ----
    if (owner) {
        #pragma unroll
        for (int q = 0; q < 4; q++) {
            int d = (dt << 5) + dl0 + 8 * q;
            float ssum = 0.f;
            #pragma unroll
            for (int z = 0; z < 4; z++) ssum += g_h0part[(z * BB + pb) * DD + d];
            float h0 = ssum / g_cntpad[pb];
            creg[q] = h0;
            hex[pb][dl0 + 8 * q] = h0;
        }
        __syncthreads();
        #pragma unroll
        for (int q = 0; q < 4; q++) {
            int i = tid + 256 * q; int b = i >> 5, dl = i & 31;
            g_hc[dt][b * 32 + dl] = hex[b][dl];
        }
        __threadfence();
        __syncthreads();
        if (tid == 0) st_release(&g_flag[dt * 32], 1u);
    }

    int tx = tid & 31;   // gate-row lane (dl)
    int ty = tid >> 5;   // b group: b = ty*4 + i

    for (int t = 0; t < NSTEP; t++) {
        // ---- stage h(t) slice [32 b][64 k] from 2 chunks ----
        #pragma unroll
        for (int cc = 0; cc < 2; cc++) {
            int ch = 2 * s + cc;
            if (owner && ch == dt) {
                #pragma unroll
                for (int q = 0; q < 4; q++) {
                    int i = tid + 256 * q; int b = i >> 5, dl = i & 31;
                    hs[b][cc * 32 + dl] = hex[b][dl];
                }
            } else {
                if (tid == 0) poll_ge(&g_flag[ch * 32], (unsigned)(t + 1));
                __syncthreads();
                #pragma unroll
                for (int q = 0; q < 2; q++) {
                    int i = tid + 256 * q; int b = i >> 4, j2 = i & 15;
                    long long v = __ldcg((const long long*)&g_hc[ch][b * 32 + j2 * 2]);
                    *(ull*)&hs[b][cc * 32 + j2 * 2] = (ull)v;
                }
            }
        }
        __syncthreads();

        // ---- GEMM: 128 gate rows x 32 b x 64 k ----
        ull acc[4][4] = {};
        #pragma unroll 8
        for (int kp = 0; kp < 32; kp++) {
            ull hv[4], wv[4];
            #pragma unroll
            for (int i = 0; i < 4; i++) hv[i] = ld2(&hs[ty * 4 + i][kp * 2]);
            #pragma unroll
            for (int j = 0; j < 4; j++) wv[j] = ld2(&Wsm[tx + 32 * j][kp * 2]);
            #pragma unroll
            for (int i = 0; i < 4; i++)
                #pragma unroll
                for (int j = 0; j < 4; j++)
                    acc[i][j] = fma2(hv[i], wv[j], acc[i][j]);
        }

        if (!owner) {
            // RED partials into g_gx[t], then arrive on cnt[dt]
            #pragma unroll
            for (int i = 0; i < 4; i++) {
                int b = ty * 4 + i;
                float* base = g_gx + ((size_t)(t * BB + b) << 11) + (dt << 5) + tx;
                #pragma unroll
                for (int j = 0; j < 4; j++)
                    red_add_f32(base + (j << 9), sum2(acc[i][j]));
            }
            __threadfence();
            __syncthreads();
            if (tid == 0)
                asm volatile("red.release.gpu.global.add.u32 [%0], 1;"
                             :: "l"(&g_cnt[dt * 32]) : "memory");
        } else {
            // keep own partial local
            #pragma unroll
            for (int i = 0; i < 4; i++)
                #pragma unroll
                for (int j = 0; j < 4; j++)
                    psum[ty * 4 + i][j][tx] = sum2(acc[i][j]);
            if (tid == 0) poll_ge(&g_cnt[dt * 32], 7u * (unsigned)(t + 1));
            __syncthreads();
            // add accumulated gates (x-side + 7 RED partials)
            #pragma unroll
            for (int q = 0; q < 16; q++) {
                int i = tid + 256 * q;
                int dl = i & 31, g = (i >> 5) & 3, b = i >> 7;
                psum[b][g][dl] += __ldcg(&g_gx[((size_t)(t * BB + b) << 11) + (g << 9) + (dt << 5) + dl]);
            }
            __syncthreads();
            // pointwise for owned (pb, d = 32dt + dl0 + 8q)
            #pragma unroll
            for (int q = 0; q < 4; q++) {
                int dl = dl0 + 8 * q;
                float gi = psum[pb][0][dl], gf = psum[pb][1][dl];
                float gg = psum[pb][2][dl], go = psum[pb][3][dl];
                float cn = sigm(gf) * creg[q] + sigm(gi) * tanhf(gg);
                float hn = sigm(go) * tanhf(cn);
                creg[q] = cn;
                hex[pb][dl] = hn;
            }
            __syncthreads();
            // publish h(t+1) chunk + Hall
            #pragma unroll
            for (int q = 0; q < 4; q++) {
                int i = tid + 256 * q; int b = i >> 5, dl = i & 31;
                float v = hex[b][dl];
                g_hc[dt][b * 32 + dl] = v;
                g_Hall[((size_t)(t * BB + b) << 9) + (dt << 5) + dl] = v;
            }
            __threadfence();
            __syncthreads();
            if (tid == 0) st_release(&g_flag[dt * 32], (unsigned)(t + 2));
        }
    }
}

// ---------------- hw: HW[m][n] = Hall[m]·W_att[n] ----------------------------
__global__ void __launch_bounds__(256) hw_kernel(const float* __restrict__ Watt) {
    __shared__ float As[64][66];
    __shared__ float Ws[64][66];
    int tid = threadIdx.x;
    int mbase = blockIdx.x * 64;
    int nbase = blockIdx.y * 64;
    int tx = tid & 15;
    int ty = tid >> 4;
    ull acc[4][4] = {};
    for (int k0 = 0; k0 < 512; k0 += 32) {
        __syncthreads();
        #pragma unroll
        for (int i = 0; i < 8; i++) {
            int lin = tid + 256 * i;
            int row = lin >> 5, c = lin & 31;
            int m = mbase + row;
            As[row][c] = (m < MM) ? g_Hall[((size_t)m << 9) + k0 + c] : 0.f;
            Ws[row][c] = Watt[(size_t)(nbase + row) * 512 + k0 + c];
        }
        __syncthreads();
        #pragma unroll
        for (int kp = 0; kp < 16; kp++) {
            ull av[4], wv[4];
            #pragma unroll
            for (int jj = 0; jj < 4; jj++) av[jj] = ld2(&As[ty * 4 + jj][kp * 2]);
            #pragma unroll
            for (int i = 0; i < 4; i++) wv[i] = ld2(&Ws[tx + 16 * i][kp * 2]);
            #pragma unroll
            for (int i = 0; i < 4; i++)
                #pragma unroll
                for (int jj = 0; jj < 4; jj++)
                    acc[i][jj] = fma2(av[jj], wv[i], acc[i][jj]);
        }
    }
    #pragma unroll
    for (int jj = 0; jj < 4; jj++) {
        int m = mbase + ty * 4 + jj;
        if (m >= MM) continue;
        #pragma unroll
        for (int i = 0; i < 4; i++)
            g_HW[((size_t)m << 9) + nbase + tx + 16 * i] = sum2(acc[i][jj]);
    }
}

// ---------------- scores[t][b][n] = enc[b][n]·HW[t*B+b] ----------------------
__global__ void __launch_bounds__(256) scores_kernel(const float* __restrict__ enc) {
    __shared__ float Es[256][34];
    __shared__ float Hs[32][34];
    int tid = threadIdx.x;
    int nbase = blockIdx.x << 8;
    int b = blockIdx.y;
    int nl = tid & 31;
    int tg = tid >> 5;
    ull acc[8][4] = {};
    for (int k0 = 0; k0 < 512; k0 += 32) {
        __syncthreads();
        #pragma unroll
        for (int i = 0; i < 16; i++) {
            int lin = tid + 256 * i;
            int row = lin >> 4, c2 = lin & 15;
            *(ull*)&Es[row][c2 * 2] =
                ld2(&enc[((size_t)(b * NN + nbase + row) << 9) + k0 + c2 * 2]);
        }
        #pragma unroll
        for (int i = 0; i < 2; i++) {
            int lin = tid + 256 * i;
            int row = lin >> 4, c2 = lin & 15;
            *(ull*)&Hs[row][c2 * 2] = (row < NSTEP)
                ? ld2(&g_HW[((size_t)(row * BB + b) << 9) + k0 + c2 * 2]) : 0ull;
        }
        __syncthreads();
        #pragma unroll
        for (int kp = 0; kp < 16; kp++) {
            ull ev[8], hv[4];
            #pragma unroll
            for (int i = 0; i < 8; i++) ev[i] = ld2(&Es[nl + 32 * i][kp * 2]);
            #pragma unroll
            for (int jj = 0; jj < 4; jj++) hv[jj] = ld2(&Hs[tg * 4 + jj][kp * 2]);
            #pragma unroll
            for (int i = 0; i < 8; i++)
                #pragma unroll
                for (int jj = 0; jj < 4; jj++)
                    acc[i][jj] = fma2(ev[i], hv[jj], acc[i][jj]);
        }
    }
    #pragma unroll
    for (int jj = 0; jj < 4; jj++) {
        int t = tg * 4 + jj;
        if (t >= NSTEP) continue;
        #pragma unroll
        for (int i = 0; i < 8; i++)
            g_scores[((size_t)(t * BB + b) << 11) + nbase + nl + 32 * i] = sum2(acc[i][jj]);
    }
}

// ---------------- softmax + threshold + scatter + eos ------------------------
__global__ void softmax_scatter_kernel(const void* ptrmask,
                                       const int* __restrict__ token_ids,
                                       const int* __restrict__ eosp,
                                       float* __restrict__ out) {
    int t = blockIdx.x, b = blockIdx.y, tid = threadIdx.x;
    __shared__ float sp[NN];
    __shared__ float red[256];
    const float* sc = g_scores + ((size_t)(t * BB) + b) * NN;

    float m = -1e30f;
    for (int n = tid; n < NN; n += 256) {
        bool pm = getmask(ptrmask, b * NN + n);
        float s = pm ? sc[n] : -1e30f;
        sp[n] = s;
        m = fmaxf(m, s);
    }
    red[tid] = m; __syncthreads();
    for (int s = 128; s > 0; s >>= 1) {
        if (tid < s) red[tid] = fmaxf(red[tid], red[tid + s]);
        __syncthreads();
    }
    m = red[0]; __syncthreads();

    float lsum = 0.f;
    for (int n = tid; n < NN; n += 256) {
        float s = sp[n];
        float e = (s > -1e29f) ? expf(s - m) : 0.f;
        sp[n] = e;
        lsum += e;
    }
    red[tid] = lsum; __syncthreads();
    for (int s = 128; s > 0; s >>= 1) {
        if (tid < s) red[tid] += red[tid + s];
        __syncthreads();
    }
    float sum = red[0];
    float thr = 1.0f / g_cntptr[b];
    float* orow = out + ((size_t)(t + 1)) * BB * VV + (size_t)b * VV;
    __syncthreads();

    float ks = 0.f;
    for (int n = tid; n < NN; n += 256) {
        float e = sp[n];
        if (e > 0.f) {
            float p = e / sum;
            if (p >= thr) {
                atomicAdd(&orow[token_ids[b * NN + n]], p);
                ks += p;
            }
        }
    }
    red[tid] = ks; __syncthreads();
    for (int s = 128; s > 0; s >>= 1) {
        if (tid < s) red[tid] += red[tid + s];
        __syncthreads();
    }
    if (tid == 0) {
        __threadfence();
        orow[eosp[0]] = 1.0f - red[0];
    }
}

// ---------------- host launcher ----------------------------------------------
extern "C" void kernel_launch(void* const* d_in, const int* in_sizes, int n_in,
                              void* d_out, int out_size) {
    const float* enc    = (const float*)d_in[0];
    const float* emb    = (const float*)d_in[1];
    const float* W_ih   = (const float*)d_in[2];
    const float* W_hh   = (const float*)d_in[3];
    const float* b_ih   = (const float*)d_in[4];
    const float* b_hh   = (const float*)d_in[5];
    const float* W_att  = (const float*)d_in[6];
    const void*  pad    = d_in[7];
    const void*  ptr    = d_in[8];
    const int*   tokid  = (const int*)d_in[9];
    const int*   target = (const int*)d_in[10];
    const int*   sosp   = (const int*)d_in[11];
    const int*   eosp   = (const int*)d_in[12];
    float* out = (float*)d_out;

    detect_kernel<<<1, 32>>>((const int*)pad);

    int n4 = (TT * BB * VV) / 4;
    zero_kernel<<<4096, 256>>>((float4*)out, n4);
    sos_kernel<<<1, 32>>>(out, sosp);

    {
        dim3 g(32, 16);
        xgemm_kernel<<<g, 256>>>(emb, W_ih, b_ih, b_hh, target, sosp);
    }

    lstm_persistent<<<128, 256>>>(W_hh, enc, pad, ptr);

    {
        dim3 g(16, 8);
        hw_kernel<<<g, 256>>>(W_att);
    }
    {
        dim3 g(8, BB);
        scores_kernel<<<g, 256>>>(enc);
    }
    {
        dim3 g(NSTEP, BB);
        softmax_scatter_kernel<<<g, 256>>>(ptr, tokid, eosp, out);
    }
}

// round 12
// speedup vs baseline: 1.4598x; 1.4598x over previous
#include <cuda_runtime.h>
#include <cuda_bf16.h>
#include <cstdint>

#define BB 32
#define NN 2048
#define DD 512
#define EE 512
#define VV 32000
#define TT 32
#define NSTEP 31
#define MM (NSTEP * BB)   // 992

typedef unsigned long long ull;

// ---------------- scratch ----------------------------------------------------
__device__ float g_h[BB * DD];
__device__ float g_Hall[MM * DD];
__device__ float g_HW[MM * DD];
__device__ float g_scores[MM * NN];         // 8.1 MB
__device__ float g_gx[MM * 4 * DD];         // 8.1 MB  (x-side gates + biases)
__device__ float g_gp[8 * BB * 4 * DD];     // 2 MB    (h-side partials)
__device__ float g_h0part[4 * BB * DD];
__device__ float g_cntpad[BB];
__device__ float g_cntptr[BB];
__device__ int   g_mask_mode;
__device__ unsigned g_barcnt;

// ---------------- helpers -----------------------------------------------------
__device__ __forceinline__ bool getmask(const void* p, int idx) {
    int m = g_mask_mode;
    if (m == 1) return ((const int*)p)[idx] != 0;
    if (m == 2) return ((const float*)p)[idx] != 0.0f;
    return ((const unsigned char*)p)[idx] != 0;
}
__device__ __forceinline__ float sigm(float x) { return 1.0f / (1.0f + expf(-x)); }

__device__ __forceinline__ ull ld2(const float* p) { return *(const ull*)p; }
__device__ __forceinline__ ull fma2(ull a, ull b, ull c) {
    ull d;
    asm("fma.rn.f32x2 %0, %1, %2, %3;" : "=l"(d) : "l"(a), "l"(b), "l"(c));
    return d;
}
__device__ __forceinline__ float sum2(ull v) {
    return __uint_as_float((unsigned)v) + __uint_as_float((unsigned)(v >> 32));
}

// ---------------- setup -------------------------------------------------------
__global__ void detect_kernel(const int* pad_as_int) {
    if (threadIdx.x == 0) {
        int v = pad_as_int[0];
        g_mask_mode = (v == 1) ? 1 : ((v == 0x3F800000) ? 2 : 0);
        g_barcnt = 0;
    }
}

__global__ void sos_kernel(float* out, const int* sosp) {
    int b = threadIdx.x;
    if (b < BB) out[(size_t)b * VV + sosp[0]] = 1.0f;
}

// ---------------- mega kernel: xgemm || h0part || counts || zero --------------
// grid 1312 x 256:
//   [0,512):    xgemm  gates_x[m][R] = emb[tok(m)]·W_ih[R] + b_ih + b_hh
//   [512,768):  h0part partial masked sums of enc
//   [768,800):  counts pad/pointer counts
//   [800,1312): zero   d_out
__global__ void __launch_bounds__(256) mega_kernel(
        const float* __restrict__ emb, const float* __restrict__ Wih,
        const float* __restrict__ bih, const float* __restrict__ bhh,
        const int* __restrict__ target, const int* __restrict__ sosp,
        const float* __restrict__ enc, const void* pad, const void* ptrm,
        float4* __restrict__ outz, int n4) {
    __shared__ float Ws[2][64][34];
    __shared__ float Xs[2][64][34];
    __shared__ int toks[64];
    __shared__ int red1[256], red2[256];
    int tid = threadIdx.x;
    int bid = blockIdx.x;

    if (bid < 512) {
        // ---------------- xgemm ----------------
        int Rbase = (bid & 31) * 64;
        int mbase = (bid >> 5) * 64;
        if (tid < 64) {
            int m = mbase + tid;
            int t = m >> 5, b = m & 31;
            int tok = sosp[0];
            if (m < MM && t > 0) tok = target[t * BB + b];
            toks[tid] = tok;
        }
        __syncthreads();
        #pragma unroll
        for (int q = 0; q < 2; q++) {
            int i = tid + 256 * q;
            int row = i >> 3, c4 = i & 7;
            float4 w = *(const float4*)&Wih[(size_t)(Rbase + row) * 512 + c4 * 4];
            float4 x = *(const float4*)&emb[(size_t)toks[row] * 512 + c4 * 4];
            *(float2*)&Ws[0][row][c4 * 4]     = make_float2(w.x, w.y);
            *(float2*)&Ws[0][row][c4 * 4 + 2] = make_float2(w.z, w.w);
            *(float2*)&Xs[0][row][c4 * 4]     = make_float2(x.x, x.y);
            *(float2*)&Xs[0][row][c4 * 4 + 2] = make_float2(x.z, x.w);
        }
        __syncthreads();
        int rl = tid & 15, mg = tid >> 4;
        ull acc[4][4] = {};
        float4 wst[2], xst[2];
        for (int kt = 0; kt < 16; kt++) {
            int cur = kt & 1;
            if (kt < 15) {
                int k0 = (kt + 1) * 32;
                #pragma unroll
                for (int q = 0; q < 2; q++) {
                    int i = tid + 256 * q;
                    int row = i >> 3, c4 = i & 7;
                    wst[q] = *(const float4*)&Wih[(size_t)(Rbase + row) * 512 + k0 + c4 * 4];
                    xst[q] = *(const float4*)&emb[(size_t)toks[row] * 512 + k0 + c4 * 4];
                }
            }
            #pragma unroll
            for (int kp = 0; kp < 16; kp++) {
                ull wv[4], xv[4];
                #pragma unroll
                for (int i = 0; i < 4; i++) wv[i] = ld2(&Ws[cur][rl + 16 * i][kp * 2]);
                #pragma unroll
                for (int j = 0; j < 4; j++) xv[j] = ld2(&Xs[cur][mg * 4 + j][kp * 2]);
                #pragma unroll
                for (int i = 0; i < 4; i++)
                    #pragma unroll
                    for (int j = 0; j < 4; j++)
                        acc[i][j] = fma2(wv[i], xv[j], acc[i][j]);
            }
            if (kt < 15) {
                __syncthreads();
                int nb = cur ^ 1;
                #pragma unroll
                for (int q = 0; q < 2; q++) {
                    int i = tid + 256 * q;
                    int row = i >> 3, c4 = i & 7;
                    *(float2*)&Ws[nb][row][c4 * 4]     = make_float2(wst[q].x, wst[q].y);
                    *(float2*)&Ws[nb][row][c4 * 4 + 2] = make_float2(wst[q].z, wst[q].w);
                    *(float2*)&Xs[nb][row][c4 * 4]     = make_float2(xst[q].x, xst[q].y);
                    *(float2*)&Xs[nb][row][c4 * 4 + 2] = make_float2(xst[q].z, xst[q].w);
                }
                __syncthreads();
            }
        }
        #pragma unroll
        for (int j = 0; j < 4; j++) {
            int m = mbase + mg * 4 + j;
            if (m >= MM) continue;
            #pragma unroll
            for (int i = 0; i < 4; i++) {
                int R = Rbase + rl + 16 * i;
                g_gx[((size_t)m << 11) + R] = sum2(acc[i][j]) + bih[R] + bhh[R];
            }
        }
    } else if (bid < 768) {
        // ---------------- h0part ----------------
        int u = bid - 512;
        int dc = u & 1, b = (u >> 1) & 31, z = u >> 6;
        int d = dc * 256 + tid;
        float acc = 0.0f;
        int n0 = z * (NN / 4);
        for (int n = n0; n < n0 + NN / 4; n++) {
            if (getmask(pad, b * NN + n))
                acc += enc[((size_t)(b * NN + n)) * DD + d];
        }
        g_h0part[((z * BB) + b) * DD + d] = acc;
    } else if (bid < 800) {
        // ---------------- counts ----------------
        int b = bid - 768;
        int c1 = 0, c2 = 0;
        for (int n = tid; n < NN; n += 256) {
            c1 += getmask(pad, b * NN + n) ? 1 : 0;
            c2 += getmask(ptrm, b * NN + n) ? 1 : 0;
        }
        red1[tid] = c1; red2[tid] = c2; __syncthreads();
        for (int s = 128; s > 0; s >>= 1) {
            if (tid < s) { red1[tid] += red1[tid + s]; red2[tid] += red2[tid + s]; }
            __syncthreads();
        }
        if (tid == 0) { g_cntpad[b] = (float)red1[0]; g_cntptr[b] = (float)red2[0]; }
    } else {
        // ---------------- zero d_out ----------------
        int zb = bid - 800;
        int idx = zb * 256 + tid;
        int stride = 512 * 256;
        float4 z4 = {0.f, 0.f, 0.f, 0.f};
        for (int i = idx; i < n4; i += stride) outz[i] = z4;
    }
}

// --------- grid barrier (R4-verbatim: RMW arrive + RMW poll) ------------------
__device__ __forceinline__ void gbar(unsigned target) {
    __threadfence();
    __syncthreads();
    if (threadIdx.x == 0) {
        atomicAdd(&g_barcnt, 1u);
        while (atomicAdd(&g_barcnt, 0u) < target) {}
        __threadfence();
    }
    __syncthreads();
}

// ---------------- persistent LSTM recurrence (R4-verbatim core) ---------------
// 128 blocks x 256 threads. block = (dt = bid>>3, s = bid&7).
__global__ void __launch_bounds__(256) lstm_persistent(const float* __restrict__ Whh) {
    __shared__ float Wsm[128][66];
    __shared__ float hs[32][66];
    int tid = threadIdx.x;
    int bid = blockIdx.x;
    int dt = bid >> 3, s = bid & 7;
    int k0 = s * 64;

    // W_hh slice into smem once
    for (int i = tid; i < 128 * 64; i += 256) {
        int lr = i >> 6, kk = i & 63;
        int R = ((lr >> 5) << 9) + (dt << 5) + (lr & 31);
        Wsm[lr][kk] = Whh[(size_t)R * 512 + k0 + kk];
    }

    // h0 finalize for owned (pb, pd)
    float creg = 0.f;
    int pd = 0, pb = 0;
    if (tid < 128) {
        int idx = bid * 128 + tid;
        pd = idx & 511; pb = idx >> 9;
        float ssum = 0.f;
        #pragma unroll
        for (int z = 0; z < 4; z++) ssum += g_h0part[(z * BB + pb) * DD + pd];
        float h0 = ssum / g_cntpad[pb];
        creg = h0;
        g_h[pb * DD + pd] = h0;
    }
    gbar(128);

    int tx = tid & 31;   // lr = tx + 32*j
    int ty = tid >> 5;   // b = ty*4 + i
    unsigned cnt = 128;

    for (int t = 0; t < NSTEP; t++) {
        // stage h slice [32 b][64 k]
        for (int i = tid; i < 32 * 64; i += 256) {
            int b = i >> 6, kk = i & 63;
            hs[b][kk] = g_h[b * DD + k0 + kk];
        }
        __syncthreads();

        ull acc[4][4] = {};
        #pragma unroll 8
        for (int kp = 0; kp < 32; kp++) {
            ull hv[4], wv[4];
            #pragma unroll
            for (int i = 0; i < 4; i++) hv[i] = ld2(&hs[ty * 4 + i][kp * 2]);
            #pragma unroll
            for (int j = 0; j < 4; j++) wv[j] = ld2(&Wsm[tx + 32 * j][kp * 2]);
            #pragma unroll
            for (int i = 0; i < 4; i++)
                #pragma unroll
                for (int j = 0; j < 4; j++)
                    acc[i][j] = fma2(hv[i], wv[j], acc[i][j]);
        }
        #pragma unroll
        for (int i = 0; i < 4; i++) {
            int b = ty * 4 + i;
            #pragma unroll
            for (int j = 0; j < 4; j++)
                g_gp[((s * BB + b) << 11) + (j << 9) + (dt << 5) + tx] = sum2(acc[i][j]);
        }

        cnt += 128; gbar(cnt);   // partials ready

        if (tid < 128) {
            const float* gx = g_gx + ((size_t)(t * BB + pb) << 11);
            float gi = gx[pd], gf = gx[512 + pd], gg = gx[1024 + pd], go = gx[1536 + pd];
            #pragma unroll
            for (int ss = 0; ss < 8; ss++) {
                const float* gp = g_gp + ((size_t)(ss * BB + pb) << 11);
                gi += gp[pd]; gf += gp[512 + pd]; gg += gp[1024 + pd]; go += gp[1536 + pd];
            }
            float cn = sigm(gf) * creg + sigm(gi) * tanhf(gg);
            float hn = sigm(go) * tanhf(cn);
            creg = cn;
            g_h[pb * DD + pd] = hn;
            g_Hall[((size_t)(t * BB + pb) << 9) + pd] = hn;
        }

        cnt += 128; gbar(cnt);   // h ready
    }
}

// ---------------- hw: HW[m][n] = Hall[m]·W_att[n] ----------------------------
__global__ void __launch_bounds__(256) hw_kernel(const float* __restrict__ Watt) {
    __shared__ float As[64][66];
    __shared__ float Ws[64][66];
    int tid = threadIdx.x;
    int mbase = blockIdx.x * 64;
    int nbase = blockIdx.y * 64;
    int tx = tid & 15;
    int ty = tid >> 4;
    ull acc[4][4] = {};
    for (int k0 = 0; k0 < 512; k0 += 32) {
        __syncthreads();
        #pragma unroll
        for (int i = 0; i < 8; i++) {
            int lin = tid + 256 * i;
            int row = lin >> 5, c = lin & 31;
            int m = mbase + row;
            As[row][c] = (m < MM) ? g_Hall[((size_t)m << 9) + k0 + c] : 0.f;
            Ws[row][c] = Watt[(size_t)(nbase + row) * 512 + k0 + c];
        }
        __syncthreads();
        #pragma unroll
        for (int kp = 0; kp < 16; kp++) {
            ull av[4], wv[4];
            #pragma unroll
            for (int jj = 0; jj < 4; jj++) av[jj] = ld2(&As[ty * 4 + jj][kp * 2]);
            #pragma unroll
            for (int i = 0; i < 4; i++) wv[i] = ld2(&Ws[tx + 16 * i][kp * 2]);
            #pragma unroll
            for (int i = 0; i < 4; i++)
                #pragma unroll
                for (int jj = 0; jj < 4; jj++)
                    acc[i][jj] = fma2(av[jj], wv[i], acc[i][jj]);
        }
    }
    #pragma unroll
    for (int jj = 0; jj < 4; jj++) {
        int m = mbase + ty * 4 + jj;
        if (m >= MM) continue;
        #pragma unroll
        for (int i = 0; i < 4; i++)
            g_HW[((size_t)m << 9) + nbase + tx + 16 * i] = sum2(acc[i][jj]);
    }
}

// ---------------- scores[t][b][n] = enc[b][n]·HW[t*B+b] ----------------------
__global__ void __launch_bounds__(256) scores_kernel(const float* __restrict__ enc) {
    __shared__ float Es[256][34];
    __shared__ float Hs[32][34];
    int tid = threadIdx.x;
    int nbase = blockIdx.x << 8;
    int b = blockIdx.y;
    int nl = tid & 31;
    int tg = tid >> 5;
    ull acc[8][4] = {};
    for (int k0 = 0; k0 < 512; k0 += 32) {
        __syncthreads();
        #pragma unroll
        for (int i = 0; i < 16; i++) {
            int lin = tid + 256 * i;
            int row = lin >> 4, c2 = lin & 15;
            *(ull*)&Es[row][c2 * 2] =
                ld2(&enc[((size_t)(b * NN + nbase + row) << 9) + k0 + c2 * 2]);
        }
        #pragma unroll
        for (int i = 0; i < 2; i++) {
            int lin = tid + 256 * i;
            int row = lin >> 4, c2 = lin & 15;
            *(ull*)&Hs[row][c2 * 2] = (row < NSTEP)
                ? ld2(&g_HW[((size_t)(row * BB + b) << 9) + k0 + c2 * 2]) : 0ull;
        }
        __syncthreads();
        #pragma unroll
        for (int kp = 0; kp < 16; kp++) {
            ull ev[8], hv[4];
            #pragma unroll
            for (int i = 0; i < 8; i++) ev[i] = ld2(&Es[nl + 32 * i][kp * 2]);
            #pragma unroll
            for (int jj = 0; jj < 4; jj++) hv[jj] = ld2(&Hs[tg * 4 + jj][kp * 2]);
            #pragma unroll
            for (int i = 0; i < 8; i++)
                #pragma unroll
                for (int jj = 0; jj < 4; jj++)
                    acc[i][jj] = fma2(ev[i], hv[jj], acc[i][jj]);
        }
    }
    #pragma unroll
    for (int jj = 0; jj < 4; jj++) {
        int t = tg * 4 + jj;
        if (t >= NSTEP) continue;
        #pragma unroll
        for (int i = 0; i < 8; i++)
            g_scores[((size_t)(t * BB + b) << 11) + nbase + nl + 32 * i] = sum2(acc[i][jj]);
    }
}

// ---------------- softmax + threshold + scatter + eos ------------------------
__global__ void softmax_scatter_kernel(const void* ptrmask,
                                       const int* __restrict__ token_ids,
                                       const int* __restrict__ eosp,
                                       float* __restrict__ out) {
    int t = blockIdx.x, b = blockIdx.y, tid = threadIdx.x;
    __shared__ float sp[NN];
    __shared__ float red[256];
    const float* sc = g_scores + ((size_t)(t * BB) + b) * NN;

    float m = -1e30f;
    for (int n = tid; n < NN; n += 256) {
        bool pm = getmask(ptrmask, b * NN + n);
        float s = pm ? sc[n] : -1e30f;
        sp[n] = s;
        m = fmaxf(m, s);
    }
    red[tid] = m; __syncthreads();
    for (int s = 128; s > 0; s >>= 1) {
        if (tid < s) red[tid] = fmaxf(red[tid], red[tid + s]);
        __syncthreads();
    }
    m = red[0]; __syncthreads();

    float lsum = 0.f;
    for (int n = tid; n < NN; n += 256) {
        float s = sp[n];
        float e = (s > -1e29f) ? expf(s - m) : 0.f;
        sp[n] = e;
        lsum += e;
    }
    red[tid] = lsum; __syncthreads();
    for (int s = 128; s > 0; s >>= 1) {
        if (tid < s) red[tid] += red[tid + s];
        __syncthreads();
    }
    float sum = red[0];
    float thr = 1.0f / g_cntptr[b];
    float* orow = out + ((size_t)(t + 1)) * BB * VV + (size_t)b * VV;
    __syncthreads();

    float ks = 0.f;
    for (int n = tid; n < NN; n += 256) {
        float e = sp[n];
        if (e > 0.f) {
            float p = e / sum;
            if (p >= thr) {
                atomicAdd(&orow[token_ids[b * NN + n]], p);
                ks += p;
            }
        }
    }
    red[tid] = ks; __syncthreads();
    for (int s = 128; s > 0; s >>= 1) {
        if (tid < s) red[tid] += red[tid + s];
        __syncthreads();
    }
    if (tid == 0) {
        __threadfence();
        orow[eosp[0]] = 1.0f - red[0];
    }
}

// ---------------- host launcher ----------------------------------------------
extern "C" void kernel_launch(void* const* d_in, const int* in_sizes, int n_in,
                              void* d_out, int out_size) {
    const float* enc    = (const float*)d_in[0];
    const float* emb    = (const float*)d_in[1];
    const float* W_ih   = (const float*)d_in[2];
    const float* W_hh   = (const float*)d_in[3];
    const float* b_ih   = (const float*)d_in[4];
    const float* b_hh   = (const float*)d_in[5];
    const float* W_att  = (const float*)d_in[6];
    const void*  pad    = d_in[7];
    const void*  ptr    = d_in[8];
    const int*   tokid  = (const int*)d_in[9];
    const int*   target = (const int*)d_in[10];
    const int*   sosp   = (const int*)d_in[11];
    const int*   eosp   = (const int*)d_in[12];
    float* out = (float*)d_out;

    detect_kernel<<<1, 32>>>((const int*)pad);

    int n4 = (TT * BB * VV) / 4;
    mega_kernel<<<1312, 256>>>(emb, W_ih, b_ih, b_hh, target, sosp,
                               enc, pad, ptr, (float4*)out, n4);
    sos_kernel<<<1, 32>>>(out, sosp);

    lstm_persistent<<<128, 256>>>(W_hh);

    {
        dim3 g(16, 8);
        hw_kernel<<<g, 256>>>(W_att);
    }
    {
        dim3 g(8, BB);
        scores_kernel<<<g, 256>>>(enc);
    }
    {
        dim3 g(NSTEP, BB);
        softmax_scatter_kernel<<<g, 256>>>(ptr, tokid, eosp, out);
    }
}